// round 1
// baseline (speedup 1.0000x reference)
#include <cuda_runtime.h>
#include <cuda_bf16.h>
#include <math.h>

// Problem constants
#define B_  32
#define S_  1024
#define D_  256
#define N_  32
#define C_  64
#define M_  (B_*S_)     // 32768
#define NC_ (N_*C_)     // 2048

// GEMM tiling
#define BM 128
#define BN 128
#define BK 32
#define SPAD 40   // smem row stride (bf16 elems) -> conflict-free frag loads

#define SCHUNK 32 // s-values per routing-pass block

// ---------------- scratch (device globals; no runtime allocation) ----------
__device__ float          g_uhat[(size_t)M_*NC_];   // 256 MiB
__device__ __nv_bfloat16  g_xhi[(size_t)M_*D_];
__device__ __nv_bfloat16  g_xlo[(size_t)M_*D_];
__device__ __nv_bfloat16  g_bhi[(size_t)NC_*D_];    // W transposed: [j=n*64+c][k]
__device__ __nv_bfloat16  g_blo[(size_t)NC_*D_];
__device__ float          g_sa[B_*NC_];
__device__ float          g_sb[B_*NC_];
__device__ float          g_v [B_*NC_];
__device__ float          g_logits[B_*S_*N_];

// ---------------- helpers ---------------------------------------------------
__device__ __forceinline__ void mma16816(float* d, const unsigned* a, const unsigned* b) {
    asm volatile(
        "mma.sync.aligned.m16n8k16.row.col.f32.bf16.bf16.f32 "
        "{%0,%1,%2,%3}, {%4,%5,%6,%7}, {%8,%9}, {%0,%1,%2,%3};\n"
        : "+f"(d[0]), "+f"(d[1]), "+f"(d[2]), "+f"(d[3])
        : "r"(a[0]), "r"(a[1]), "r"(a[2]), "r"(a[3]), "r"(b[0]), "r"(b[1]));
}

// ---------------- prep ------------------------------------------------------
__global__ void zero_init_kernel() {
    int i = blockIdx.x * blockDim.x + threadIdx.x;
    if (i < B_*NC_) { g_sa[i] = 0.f; g_sb[i] = 0.f; }
}

__global__ void prep_x_kernel(const float* __restrict__ x) {
    int i = (blockIdx.x * blockDim.x + threadIdx.x) * 4;
    if (i < M_*D_) {
        #pragma unroll
        for (int k = 0; k < 4; k++) {
            float v = x[i + k];
            __nv_bfloat16 h = __float2bfloat16(v);
            g_xhi[i + k] = h;
            g_xlo[i + k] = __float2bfloat16(v - __bfloat162float(h));
        }
    }
}

__global__ void prep_w_kernel(const float* __restrict__ W) {
    int o = blockIdx.x * blockDim.x + threadIdx.x;  // over NC_*D_
    if (o < NC_*D_) {
        int j = o >> 8;          // D_ = 256
        int k = o & 255;
        int n = j >> 6, c = j & 63;
        float v = W[n*D_*C_ + k*C_ + c];
        __nv_bfloat16 h = __float2bfloat16(v);
        g_bhi[o] = h;
        g_blo[o] = __float2bfloat16(v - __bfloat162float(h));
    }
}

// ---------------- split-bf16 GEMM: u_hat = x @ Wt, fused s0 epilogue --------
__global__ __launch_bounds__(256, 1) void gemm_kernel() {
    __shared__ __align__(16) __nv_bfloat16 sAh[BM][SPAD];
    __shared__ __align__(16) __nv_bfloat16 sAl[BM][SPAD];
    __shared__ __align__(16) __nv_bfloat16 sBh[BN][SPAD];
    __shared__ __align__(16) __nv_bfloat16 sBl[BN][SPAD];

    const int tid  = threadIdx.x;
    const int warp = tid >> 5, lane = tid & 31;
    const int wm = warp >> 2, wn = warp & 3;      // 2x4 warp grid
    const int g  = lane >> 2, tg = lane & 3;
    const int row0 = blockIdx.y * BM;
    const int col0 = blockIdx.x * BN;

    // stage mapping: 2 float4 per array per thread
    const int f0 = tid * 2, f1 = tid * 2 + 1;
    const int r0 = f0 >> 2, kq0 = f0 & 3;
    const int r1 = f1 >> 2, kq1 = f1 & 3;

    float acc[4][4][4];
    #pragma unroll
    for (int a = 0; a < 4; a++)
        #pragma unroll
        for (int b = 0; b < 4; b++)
            #pragma unroll
            for (int c = 0; c < 4; c++) acc[a][b][c] = 0.f;

    float4 st[8];
    auto stage_load = [&](int kc) {
        size_t ko = (size_t)kc * BK;
        st[0] = *(const float4*)(g_xhi + (size_t)(row0 + r0) * D_ + ko + kq0 * 8);
        st[1] = *(const float4*)(g_xhi + (size_t)(row0 + r1) * D_ + ko + kq1 * 8);
        st[2] = *(const float4*)(g_xlo + (size_t)(row0 + r0) * D_ + ko + kq0 * 8);
        st[3] = *(const float4*)(g_xlo + (size_t)(row0 + r1) * D_ + ko + kq1 * 8);
        st[4] = *(const float4*)(g_bhi + (size_t)(col0 + r0) * D_ + ko + kq0 * 8);
        st[5] = *(const float4*)(g_bhi + (size_t)(col0 + r1) * D_ + ko + kq1 * 8);
        st[6] = *(const float4*)(g_blo + (size_t)(col0 + r0) * D_ + ko + kq0 * 8);
        st[7] = *(const float4*)(g_blo + (size_t)(col0 + r1) * D_ + ko + kq1 * 8);
    };
    auto stage_store = [&]() {
        *(float4*)&sAh[r0][kq0 * 8] = st[0];  *(float4*)&sAh[r1][kq1 * 8] = st[1];
        *(float4*)&sAl[r0][kq0 * 8] = st[2];  *(float4*)&sAl[r1][kq1 * 8] = st[3];
        *(float4*)&sBh[r0][kq0 * 8] = st[4];  *(float4*)&sBh[r1][kq1 * 8] = st[5];
        *(float4*)&sBl[r0][kq0 * 8] = st[6];  *(float4*)&sBl[r1][kq1 * 8] = st[7];
    };

    stage_load(0); stage_store(); __syncthreads();

    const int NKC = D_ / BK;  // 8
    for (int kc = 0; kc < NKC; kc++) {
        if (kc + 1 < NKC) stage_load(kc + 1);

        #pragma unroll
        for (int ks = 0; ks < 2; ks++) {
            const int kb = ks * 16;
            unsigned ah[4][4], al[4][4];
            #pragma unroll
            for (int mt = 0; mt < 4; mt++) {
                int r = wm * 64 + mt * 16 + g;
                ah[mt][0] = *(const unsigned*)&sAh[r    ][kb + tg * 2];
                ah[mt][1] = *(const unsigned*)&sAh[r + 8][kb + tg * 2];
                ah[mt][2] = *(const unsigned*)&sAh[r    ][kb + tg * 2 + 8];
                ah[mt][3] = *(const unsigned*)&sAh[r + 8][kb + tg * 2 + 8];
                al[mt][0] = *(const unsigned*)&sAl[r    ][kb + tg * 2];
                al[mt][1] = *(const unsigned*)&sAl[r + 8][kb + tg * 2];
                al[mt][2] = *(const unsigned*)&sAl[r    ][kb + tg * 2 + 8];
                al[mt][3] = *(const unsigned*)&sAl[r + 8][kb + tg * 2 + 8];
            }
            unsigned bh[4][2], bl[4][2];
            #pragma unroll
            for (int nt = 0; nt < 4; nt++) {
                int cj = wn * 32 + nt * 8 + g;
                bh[nt][0] = *(const unsigned*)&sBh[cj][kb + tg * 2];
                bh[nt][1] = *(const unsigned*)&sBh[cj][kb + tg * 2 + 8];
                bl[nt][0] = *(const unsigned*)&sBl[cj][kb + tg * 2];
                bl[nt][1] = *(const unsigned*)&sBl[cj][kb + tg * 2 + 8];
            }
            #pragma unroll
            for (int mt = 0; mt < 4; mt++)
                #pragma unroll
                for (int nt = 0; nt < 4; nt++) {
                    mma16816(acc[mt][nt], ah[mt], bh[nt]);  // hi*hi
                    mma16816(acc[mt][nt], ah[mt], bl[nt]);  // hi*lo
                    mma16816(acc[mt][nt], al[mt], bh[nt]);  // lo*hi
                }
        }
        __syncthreads();
        if (kc + 1 < NKC) { stage_store(); __syncthreads(); }
    }

    // epilogue: write u_hat
    #pragma unroll
    for (int mt = 0; mt < 4; mt++)
        #pragma unroll
        for (int nt = 0; nt < 4; nt++) {
            int r  = row0 + wm * 64 + mt * 16 + g;
            int cj = col0 + wn * 32 + nt * 8 + tg * 2;
            *(float2*)&g_uhat[(size_t)r * NC_ + cj]       = make_float2(acc[mt][nt][0], acc[mt][nt][1]);
            *(float2*)&g_uhat[(size_t)(r + 8) * NC_ + cj] = make_float2(acc[mt][nt][2], acc[mt][nt][3]);
        }

    // fused s0 = (1/N) * sum_s u_hat   (iter-0 coupling is uniform softmax(0))
    const int bb = row0 / S_;  // whole tile lies in one b (1024 % 128 == 0)
    #pragma unroll
    for (int nt = 0; nt < 4; nt++) {
        float s0v = 0.f, s1v = 0.f;
        #pragma unroll
        for (int mt = 0; mt < 4; mt++) {
            s0v += acc[mt][nt][0] + acc[mt][nt][2];
            s1v += acc[mt][nt][1] + acc[mt][nt][3];
        }
        #pragma unroll
        for (int o = 4; o < 32; o <<= 1) {
            s0v += __shfl_xor_sync(0xffffffffu, s0v, o);
            s1v += __shfl_xor_sync(0xffffffffu, s1v, o);
        }
        if (lane < 4) {
            int cj = col0 + wn * 32 + nt * 8 + tg * 2;
            atomicAdd(&g_sa[bb * NC_ + cj],     s0v * (1.0f / (float)N_));
            atomicAdd(&g_sa[bb * NC_ + cj + 1], s1v * (1.0f / (float)N_));
        }
    }
}

// ---------------- squash ----------------------------------------------------
// grid = B_*N_, block = 32.  src_sel: 0 -> g_sa, 1 -> g_sb.
// zero_sel != 0 -> also zero g_sa (prep for next accumulation pass).
// ext_out != nullptr -> write there instead of g_v (final output).
__global__ void squash_kernel(int src_sel, int zero_sel, float* ext_out) {
    int row  = blockIdx.x;       // b*N_ + n
    int lane = threadIdx.x;
    const float* s = src_sel ? g_sb : g_sa;
    float x0 = s[row * C_ + lane];
    float x1 = s[row * C_ + 32 + lane];
    float ss = x0 * x0 + x1 * x1;
    #pragma unroll
    for (int o = 16; o > 0; o >>= 1) ss += __shfl_xor_sync(0xffffffffu, ss, o);
    float scale = (ss / (1.f + ss)) * rsqrtf(ss + 1e-8f);
    float* o = ext_out ? ext_out : g_v;
    o[row * C_ + lane]      = x0 * scale;
    o[row * C_ + 32 + lane] = x1 * scale;
    if (zero_sel) {
        g_sa[row * C_ + lane]      = 0.f;
        g_sa[row * C_ + 32 + lane] = 0.f;
    }
}

// ---------------- fused routing pass ----------------------------------------
// One block = one b and SCHUNK consecutive s values. 256 threads, 8 floats each.
// Computes agreement with g_v, updates logits, softmax over N (warp 0),
// accumulates s_next in registers, one atomicAdd sweep at the end.
__global__ __launch_bounds__(256) void pass_kernel(int sout_sel /*1->g_sb*/, int first) {
    __shared__ float sv[NC_];
    __shared__ float sagree[N_];
    __shared__ float scoef[N_];

    const int tid = threadIdx.x;
    const int bpb = S_ / SCHUNK;                    // blocks per b
    const int b   = blockIdx.x / bpb;
    const int s0i = (blockIdx.x % bpb) * SCHUNK;

    for (int i = tid; i < NC_; i += 256) sv[i] = g_v[b * NC_ + i];
    __syncthreads();

    const int j0 = tid * 8;
    const int ng = tid >> 3;                        // n index owned by this 8-group
    const float* up = g_uhat + ((size_t)(b * S_ + s0i)) * NC_ + j0;

    float u[8], acc[8];
    #pragma unroll
    for (int i = 0; i < 8; i++) acc[i] = 0.f;
    *(float4*)&u[0] = *(const float4*)(up);
    *(float4*)&u[4] = *(const float4*)(up + 4);

    for (int s = 0; s < SCHUNK; s++) {
        float uc[8];
        #pragma unroll
        for (int i = 0; i < 8; i++) uc[i] = u[i];
        if (s + 1 < SCHUNK) {
            const float* upn = up + (size_t)(s + 1) * NC_;
            *(float4*)&u[0] = *(const float4*)(upn);
            *(float4*)&u[4] = *(const float4*)(upn + 4);
        }

        float dot = 0.f;
        #pragma unroll
        for (int i = 0; i < 8; i++) dot += uc[i] * sv[j0 + i];
        dot += __shfl_down_sync(0xffffffffu, dot, 4, 8);
        dot += __shfl_down_sync(0xffffffffu, dot, 2, 8);
        dot += __shfl_down_sync(0xffffffffu, dot, 1, 8);
        if ((tid & 7) == 0) sagree[ng] = dot;
        __syncthreads();

        if (tid < N_) {
            int li = (b * S_ + s0i + s) * N_ + tid;
            float lg = sagree[tid];
            if (!first) lg += g_logits[li];
            if (first)  g_logits[li] = lg;          // pass 2 reads it
            float mx = lg;
            #pragma unroll
            for (int o = 16; o > 0; o >>= 1) mx = fmaxf(mx, __shfl_xor_sync(0xffffffffu, mx, o));
            float e = expf(lg - mx);
            float sum = e;
            #pragma unroll
            for (int o = 16; o > 0; o >>= 1) sum += __shfl_xor_sync(0xffffffffu, sum, o);
            scoef[tid] = e / sum;
        }
        __syncthreads();

        float cw = scoef[ng];
        #pragma unroll
        for (int i = 0; i < 8; i++) acc[i] += cw * uc[i];
    }

    float* so = sout_sel ? g_sb : g_sa;
    #pragma unroll
    for (int i = 0; i < 8; i++) atomicAdd(&so[b * NC_ + j0 + i], acc[i]);
}

// ---------------- launch ----------------------------------------------------
extern "C" void kernel_launch(void* const* d_in, const int* in_sizes, int n_in,
                              void* d_out, int out_size) {
    (void)in_sizes; (void)n_in; (void)out_size;
    const float* x = (const float*)d_in[0];
    const float* W = (const float*)d_in[1];
    float* out = (float*)d_out;

    zero_init_kernel<<<(B_*NC_ + 255) / 256, 256>>>();
    prep_x_kernel<<<(M_*D_) / (256 * 4), 256>>>(x);
    prep_w_kernel<<<(NC_*D_ + 255) / 256, 256>>>(W);

    dim3 grid(NC_ / BN, M_ / BM);
    gemm_kernel<<<grid, 256>>>();                       // u_hat + s0

    squash_kernel<<<B_*N_, 32>>>(0, 0, nullptr);        // v0 = squash(s0)
    pass_kernel<<<B_ * (S_ / SCHUNK), 256>>>(1, 1);     // iter1 -> s1 (g_sb), logits
    squash_kernel<<<B_*N_, 32>>>(1, 1, nullptr);        // v1, zero g_sa
    pass_kernel<<<B_ * (S_ / SCHUNK), 256>>>(0, 0);     // iter2 -> s2 (g_sa)
    squash_kernel<<<B_*N_, 32>>>(0, 0, out);            // v2 -> d_out
}

// round 4
// speedup vs baseline: 3.4093x; 3.4093x over previous
#include <cuda_runtime.h>
#include <math.h>
#include <stdint.h>

// Problem constants
#define B_  32
#define S_  1024
#define D_  256
#define N_  32
#define C_  64

// pass kernel tiling
#define SCH 64                // s-values per block
#define CHUNKS (S_/SCH)       // 16
#define XPAD 260              // xS row stride (floats) — full D_ row + skew
#define PPAD 260              // pS row stride
#define CPAD 36               // agree/coef row stride
#define WPAD 65               // W smem row stride (capsule)

#define PASS_SMEM  ((SCH*XPAD + N_*PPAD + SCH*CPAD) * 4)          // 109056 B
#define CAPS_SMEM  ((D_*WPAD + 8*D_ + 8*C_ + 8*C_) * 4)           // 78848 B

// ---------------- scratch (device globals; no runtime allocation) ----------
__device__ float g_y0[B_*D_];          // (1/N) * sum_s x
__device__ float g_ya[B_*N_*D_];       // y for iter1
__device__ float g_yb[B_*N_*D_];       // y for iter2
__device__ float g_v [B_*N_*C_];
__device__ float g_p [B_*N_*D_];       // p[b,n,d] = sum_c W[n,d,c] v[b,n,c]
__device__ float g_logits[B_*S_*N_];

// ---------------- zero ------------------------------------------------------
__global__ void zero_kernel() {
    int i = blockIdx.x * blockDim.x + threadIdx.x;
    if (i < B_*D_) g_y0[i] = 0.f;
    if (i < B_*N_*D_) { g_ya[i] = 0.f; g_yb[i] = 0.f; }
}

// ---------------- y0 = (1/N) * sum_s x --------------------------------------
__global__ __launch_bounds__(256) void reduce_x_kernel(const float* __restrict__ x) {
    const int b  = blockIdx.x >> 3;     // 32
    const int sg = blockIdx.x & 7;      // 8 groups x 128 s
    const int d  = threadIdx.x;
    const float* xp = x + ((size_t)b * S_ + sg * 128) * D_ + d;
    float a0 = 0.f, a1 = 0.f, a2 = 0.f, a3 = 0.f;
    #pragma unroll 8
    for (int s = 0; s < 128; s += 4) {
        a0 += xp[(s+0)*D_]; a1 += xp[(s+1)*D_];
        a2 += xp[(s+2)*D_]; a3 += xp[(s+3)*D_];
    }
    atomicAdd(&g_y0[b*D_ + d], (a0+a1+a2+a3) * (1.0f / (float)N_));
}

// ---------------- capsule: s = y@W, v = squash(s), p = W@v -------------------
// grid (N_, B_/8), 256 threads. ysel: 0->g_y0 (n-uniform), 1->g_ya, 2->g_yb.
__global__ __launch_bounds__(256) void capsule_kernel(const float* __restrict__ W,
                                                      int ysel, float* __restrict__ vout_ext,
                                                      int compute_p) {
    extern __shared__ float sm[];
    float* sW = sm;                 // [D_][WPAD]
    float* sy = sW + D_*WPAD;       // [8][D_]
    float* ss = sy + 8*D_;          // [8][C_]
    float* sv = ss + 8*C_;          // [8][C_]

    const int n  = blockIdx.x;
    const int b0 = blockIdx.y * 8;
    const int t  = threadIdx.x;

    // load W[n] (16384 floats), padded rows
    const float* Wn = W + (size_t)n * D_ * C_;
    for (int i = t; i < D_*C_; i += 256) {
        int d = i >> 6, c = i & 63;
        sW[d*WPAD + c] = Wn[i];
    }
    // load y rows for 8 b's
    const float* ysrc = (ysel == 0) ? g_y0 : (ysel == 1) ? g_ya : g_yb;
    for (int i = t; i < 8*D_; i += 256) {
        int bb = i >> 8, d = i & 255;
        sy[bb*D_ + d] = (ysel == 0) ? ysrc[(b0+bb)*D_ + d]
                                    : ysrc[((size_t)(b0+bb)*N_ + n)*D_ + d];
    }
    __syncthreads();

    // s[b][c] = sum_d y[b][d] * W[d][c]; thread: c = t&63, b = 2*(t>>6)+{0,1}
    {
        const int c = t & 63, bt = t >> 6;
        float s0 = 0.f, s1 = 0.f;
        const float* y0r = sy + (bt*2+0)*D_;
        const float* y1r = sy + (bt*2+1)*D_;
        #pragma unroll 4
        for (int d = 0; d < D_; d++) {
            float w = sW[d*WPAD + c];
            s0 += y0r[d] * w;
            s1 += y1r[d] * w;
        }
        ss[(bt*2+0)*C_ + c] = s0;
        ss[(bt*2+1)*C_ + c] = s1;
    }
    __syncthreads();

    // squash: warp wid handles b = b0+wid
    const int wid = t >> 5, lane = t & 31;
    {
        float a0 = ss[wid*C_ + lane];
        float a1 = ss[wid*C_ + 32 + lane];
        float sq = a0*a0 + a1*a1;
        #pragma unroll
        for (int o = 16; o > 0; o >>= 1) sq += __shfl_xor_sync(0xffffffffu, sq, o);
        float sc = (sq / (1.f + sq)) * rsqrtf(sq + 1e-8f);
        float v0 = a0 * sc, v1 = a1 * sc;
        sv[wid*C_ + lane]      = v0;
        sv[wid*C_ + 32 + lane] = v1;
        float* vo = (vout_ext ? vout_ext : g_v) + ((size_t)(b0+wid)*N_ + n)*C_;
        vo[lane]      = v0;
        vo[32 + lane] = v1;
    }
    __syncthreads();

    // p[b][d] = sum_c W[d][c] * v[b][c]; thread: b = t>>5, d = dd*32 + (t&31)
    if (compute_p) {
        const int b = t >> 5, dl = t & 31;
        const float* vb = sv + b*C_;
        #pragma unroll
        for (int dd = 0; dd < 8; dd++) {
            int d = dd*32 + dl;
            const float* wr = sW + d*WPAD;
            float acc = 0.f;
            #pragma unroll
            for (int cc = 0; cc < C_; cc++) acc += wr[cc] * vb[cc];
            g_p[((size_t)(b0+b)*N_ + n)*D_ + d] = acc;
        }
    }
}

// ---------------- fused routing pass ----------------------------------------
// grid = B_*CHUNKS (512), 256 threads, 2 CTAs/SM.
// agree = x@p^T; logits update; softmax over n; y += c^T x (atomics).
__global__ __launch_bounds__(256, 2) void pass_kernel(const float* __restrict__ x, int first) {
    extern __shared__ float sm[];
    float* xS = sm;                    // [SCH][XPAD]
    float* pS = xS + SCH*XPAD;         // [N_][PPAD]
    float* cS = pS + N_*PPAD;          // [SCH][CPAD]  (agree, then coefficients)

    const int t  = threadIdx.x;
    const int b  = blockIdx.x >> 4;    // CHUNKS = 16
    const int ch = blockIdx.x & 15;
    const int s0 = ch * SCH;

    // load x chunk: SCH rows x 64 float4, coalesced
    {
        const float4* xg = (const float4*)(x + ((size_t)b * S_ + s0) * D_);
        for (int i = t; i < SCH*(D_/4); i += 256) {
            int s = i >> 6, dq = i & 63;
            *(float4*)&xS[s*XPAD + dq*4] = xg[i];
        }
    }
    // load p[b]: N_ rows x 64 float4
    {
        const float4* pg = (const float4*)(g_p + (size_t)b * N_ * D_);
        for (int i = t; i < N_*(D_/4); i += 256) {
            int n = i >> 6, dq = i & 63;
            *(float4*)&pS[n*PPAD + dq*4] = pg[i];
        }
    }
    __syncthreads();

    // phase 2: agree tile 4s x 2n per thread
    {
        const int sg = t >> 4;          // 0..15 -> rows 4*sg..+3
        const int ng = t & 15;          // 0..15 -> cols 2*ng, 2*ng+1
        float ag[4][2];
        #pragma unroll
        for (int i = 0; i < 4; i++) { ag[i][0] = 0.f; ag[i][1] = 0.f; }
        #pragma unroll 2
        for (int dq = 0; dq < 64; dq++) {
            float4 p0 = *(const float4*)&pS[(2*ng+0)*PPAD + dq*4];
            float4 p1 = *(const float4*)&pS[(2*ng+1)*PPAD + dq*4];
            #pragma unroll
            for (int i = 0; i < 4; i++) {
                float4 xv = *(const float4*)&xS[(4*sg+i)*XPAD + dq*4];
                ag[i][0] += xv.x*p0.x + xv.y*p0.y + xv.z*p0.z + xv.w*p0.w;
                ag[i][1] += xv.x*p1.x + xv.y*p1.y + xv.z*p1.z + xv.w*p1.w;
            }
        }
        #pragma unroll
        for (int i = 0; i < 4; i++) {
            cS[(4*sg+i)*CPAD + 2*ng+0] = ag[i][0];
            cS[(4*sg+i)*CPAD + 2*ng+1] = ag[i][1];
        }
    }
    __syncthreads();

    // softmax over n per s-row; logits store (pass1) / accumulate (pass2)
    {
        const int wid = t >> 5, lane = t & 31;
        #pragma unroll
        for (int r = 0; r < SCH/8; r++) {
            int s = wid * (SCH/8) + r;
            float lg = cS[s*CPAD + lane];
            size_t li = ((size_t)b * S_ + s0 + s) * N_ + lane;
            if (first) g_logits[li] = lg;
            else       lg += g_logits[li];
            float mx = lg;
            #pragma unroll
            for (int o = 16; o > 0; o >>= 1) mx = fmaxf(mx, __shfl_xor_sync(0xffffffffu, mx, o));
            float e = expf(lg - mx);
            float sum = e;
            #pragma unroll
            for (int o = 16; o > 0; o >>= 1) sum += __shfl_xor_sync(0xffffffffu, sum, o);
            cS[s*CPAD + lane] = e / sum;
        }
    }
    __syncthreads();

    // phase 3: y[n][d] += sum_s c[s][n] * x[s][d]; thread tile 4n x 8d
    {
        const int ng2 = t >> 5;         // 0..7 -> n0 = 4*ng2
        const int dg  = t & 31;         // d0 = 8*dg
        float acc[4][8];
        #pragma unroll
        for (int i = 0; i < 4; i++)
            #pragma unroll
            for (int j = 0; j < 8; j++) acc[i][j] = 0.f;
        #pragma unroll 2
        for (int s = 0; s < SCH; s++) {
            float4 xa = *(const float4*)&xS[s*XPAD + dg*8];
            float4 xb = *(const float4*)&xS[s*XPAD + dg*8 + 4];
            float4 cv = *(const float4*)&cS[s*CPAD + ng2*4];
            float xr[8] = {xa.x, xa.y, xa.z, xa.w, xb.x, xb.y, xb.z, xb.w};
            float cr[4] = {cv.x, cv.y, cv.z, cv.w};
            #pragma unroll
            for (int i = 0; i < 4; i++)
                #pragma unroll
                for (int j = 0; j < 8; j++) acc[i][j] += cr[i] * xr[j];
        }
        float* yo = (first ? g_ya : g_yb) + (size_t)b * N_ * D_;
        #pragma unroll
        for (int i = 0; i < 4; i++)
            #pragma unroll
            for (int j = 0; j < 8; j++)
                atomicAdd(&yo[(ng2*4 + i)*D_ + dg*8 + j], acc[i][j]);
    }
}

// ---------------- launch ----------------------------------------------------
extern "C" void kernel_launch(void* const* d_in, const int* in_sizes, int n_in,
                              void* d_out, int out_size) {
    (void)in_sizes; (void)n_in; (void)out_size;
    const float* x = (const float*)d_in[0];
    const float* W = (const float*)d_in[1];
    float* out = (float*)d_out;

    cudaFuncSetAttribute(capsule_kernel, cudaFuncAttributeMaxDynamicSharedMemorySize, CAPS_SMEM);
    cudaFuncSetAttribute(pass_kernel,    cudaFuncAttributeMaxDynamicSharedMemorySize, PASS_SMEM);

    zero_kernel<<<(B_*N_*D_ + 255) / 256, 256>>>();
    reduce_x_kernel<<<B_*8, 256>>>(x);                                  // y0

    capsule_kernel<<<dim3(N_, B_/8), 256, CAPS_SMEM>>>(W, 0, nullptr, 1); // v0, p0
    pass_kernel<<<B_*CHUNKS, 256, PASS_SMEM>>>(x, 1);                     // iter1 -> g_ya, logits
    capsule_kernel<<<dim3(N_, B_/8), 256, CAPS_SMEM>>>(W, 1, nullptr, 1); // v1, p1
    pass_kernel<<<B_*CHUNKS, 256, PASS_SMEM>>>(x, 0);                     // iter2 -> g_yb
    capsule_kernel<<<dim3(N_, B_/8), 256, CAPS_SMEM>>>(W, 2, out, 0);     // v2 -> d_out
}

// round 5
// speedup vs baseline: 3.9643x; 1.1628x over previous
#include <cuda_runtime.h>
#include <math.h>
#include <stdint.h>

// Problem constants
#define B_  32
#define S_  1024
#define D_  256
#define N_  32
#define C_  64

// pass kernel tiling
#define SCH 64                // s-values per block
#define CHUNKS (S_/SCH)       // 16
#define TPB 512               // threads per pass block
#define XPAD 260              // xS row stride (floats) — full D_ row + skew
#define PPAD 260              // pS row stride
#define CPAD 36               // agree/coef row stride
#define WPAD 65               // W smem row stride (capsule)

#define PASS_SMEM  ((SCH*XPAD + N_*PPAD + SCH*CPAD) * 4)          // 109056 B
#define CAPS_SMEM  ((D_*WPAD + 8*D_ + 8*C_ + 8*C_) * 4)           // 78848 B

// ---------------- scratch (device globals; no runtime allocation) ----------
__device__ float g_y0[B_*D_];          // (1/N) * sum_s x
__device__ float g_ya[B_*N_*D_];       // y for iter1
__device__ float g_yb[B_*N_*D_];       // y for iter2
__device__ float g_v [B_*N_*C_];
__device__ float g_p [B_*N_*D_];       // p[b,n,d] = sum_c W[n,d,c] v[b,n,c]
__device__ float g_logits[B_*S_*N_];

// ---------------- zero ------------------------------------------------------
__global__ void zero_kernel() {
    int i = blockIdx.x * blockDim.x + threadIdx.x;
    if (i < B_*D_) g_y0[i] = 0.f;
    if (i < B_*N_*D_) { g_ya[i] = 0.f; g_yb[i] = 0.f; }
}

// ---------------- y0 = (1/N) * sum_s x --------------------------------------
__global__ __launch_bounds__(256) void reduce_x_kernel(const float* __restrict__ x) {
    const int b  = blockIdx.x >> 3;     // 32
    const int sg = blockIdx.x & 7;      // 8 groups x 128 s
    const int d  = threadIdx.x;
    const float* xp = x + ((size_t)b * S_ + sg * 128) * D_ + d;
    float a0 = 0.f, a1 = 0.f, a2 = 0.f, a3 = 0.f;
    #pragma unroll 8
    for (int s = 0; s < 128; s += 4) {
        a0 += xp[(s+0)*D_]; a1 += xp[(s+1)*D_];
        a2 += xp[(s+2)*D_]; a3 += xp[(s+3)*D_];
    }
    atomicAdd(&g_y0[b*D_ + d], (a0+a1+a2+a3) * (1.0f / (float)N_));
}

// ---------------- capsule: s = y@W, v = squash(s), p = W@v -------------------
// grid (N_, B_/8), 256 threads. ysel: 0->g_y0 (n-uniform), 1->g_ya, 2->g_yb.
__global__ __launch_bounds__(256) void capsule_kernel(const float* __restrict__ W,
                                                      int ysel, float* __restrict__ vout_ext,
                                                      int compute_p) {
    extern __shared__ float sm[];
    float* sW = sm;                 // [D_][WPAD]
    float* sy = sW + D_*WPAD;       // [8][D_]
    float* ss = sy + 8*D_;          // [8][C_]
    float* sv = ss + 8*C_;          // [8][C_]

    const int n  = blockIdx.x;
    const int b0 = blockIdx.y * 8;
    const int t  = threadIdx.x;

    const float* Wn = W + (size_t)n * D_ * C_;
    for (int i = t; i < D_*C_; i += 256) {
        int d = i >> 6, c = i & 63;
        sW[d*WPAD + c] = Wn[i];
    }
    const float* ysrc = (ysel == 0) ? g_y0 : (ysel == 1) ? g_ya : g_yb;
    for (int i = t; i < 8*D_; i += 256) {
        int bb = i >> 8, d = i & 255;
        sy[bb*D_ + d] = (ysel == 0) ? ysrc[(b0+bb)*D_ + d]
                                    : ysrc[((size_t)(b0+bb)*N_ + n)*D_ + d];
    }
    __syncthreads();

    // s[b][c] = sum_d y[b][d] * W[d][c]
    {
        const int c = t & 63, bt = t >> 6;
        float s0 = 0.f, s1 = 0.f;
        const float* y0r = sy + (bt*2+0)*D_;
        const float* y1r = sy + (bt*2+1)*D_;
        #pragma unroll 4
        for (int d = 0; d < D_; d++) {
            float w = sW[d*WPAD + c];
            s0 += y0r[d] * w;
            s1 += y1r[d] * w;
        }
        ss[(bt*2+0)*C_ + c] = s0;
        ss[(bt*2+1)*C_ + c] = s1;
    }
    __syncthreads();

    // squash: warp wid handles b = b0+wid
    const int wid = t >> 5, lane = t & 31;
    {
        float a0 = ss[wid*C_ + lane];
        float a1 = ss[wid*C_ + 32 + lane];
        float sq = a0*a0 + a1*a1;
        #pragma unroll
        for (int o = 16; o > 0; o >>= 1) sq += __shfl_xor_sync(0xffffffffu, sq, o);
        float sc = (sq / (1.f + sq)) * rsqrtf(sq + 1e-8f);
        float v0 = a0 * sc, v1 = a1 * sc;
        sv[wid*C_ + lane]      = v0;
        sv[wid*C_ + 32 + lane] = v1;
        float* vo = (vout_ext ? vout_ext : g_v) + ((size_t)(b0+wid)*N_ + n)*C_;
        vo[lane]      = v0;
        vo[32 + lane] = v1;
    }
    __syncthreads();

    // p[b][d] = sum_c W[d][c] * v[b][c]
    if (compute_p) {
        const int b = t >> 5, dl = t & 31;
        const float* vb = sv + b*C_;
        #pragma unroll
        for (int dd = 0; dd < 8; dd++) {
            int d = dd*32 + dl;
            const float* wr = sW + d*WPAD;
            float acc = 0.f;
            #pragma unroll
            for (int cc = 0; cc < C_; cc++) acc += wr[cc] * vb[cc];
            g_p[((size_t)(b0+b)*N_ + n)*D_ + d] = acc;
        }
    }
}

// ---------------- fused routing pass ----------------------------------------
// grid = B_*CHUNKS (512), 512 threads, 2 CTAs/SM.
// agree = x@p^T; logits update; softmax over n; y += c^T x (atomics).
__global__ __launch_bounds__(TPB, 2) void pass_kernel(const float* __restrict__ x, int first) {
    extern __shared__ float sm[];
    float* xS = sm;                    // [SCH][XPAD]
    float* pS = xS + SCH*XPAD;         // [N_][PPAD]
    float* cS = pS + N_*PPAD;          // [SCH][CPAD]  (agree, then coefficients)

    const int t  = threadIdx.x;
    const int b  = blockIdx.x >> 4;    // CHUNKS = 16
    const int ch = blockIdx.x & 15;
    const int s0 = ch * SCH;

    // load x chunk: SCH rows x 64 float4, coalesced
    {
        const float4* xg = (const float4*)(x + ((size_t)b * S_ + s0) * D_);
        for (int i = t; i < SCH*(D_/4); i += TPB) {
            int s = i >> 6, dq = i & 63;
            *(float4*)&xS[s*XPAD + dq*4] = xg[i];
        }
    }
    // load p[b]: N_ rows x 64 float4
    {
        const float4* pg = (const float4*)(g_p + (size_t)b * N_ * D_);
        for (int i = t; i < N_*(D_/4); i += TPB) {
            int n = i >> 6, dq = i & 63;
            *(float4*)&pS[n*PPAD + dq*4] = pg[i];
        }
    }
    __syncthreads();

    // phase 2: agree tile 2s x 2n per thread.
    // n-cols = {ng, ng+16}: p row-step PPAD*16 floats -> 8 lanes span all 8
    // bank-groups (conflict-free); x reads are warp-broadcast.
    {
        const int sg = t >> 4;          // 0..31 -> rows 2sg, 2sg+1
        const int ng = t & 15;          // cols ng, ng+16
        float ag[2][2];
        ag[0][0] = ag[0][1] = ag[1][0] = ag[1][1] = 0.f;
        #pragma unroll 4
        for (int dq = 0; dq < 64; dq++) {
            float4 p0 = *(const float4*)&pS[(ng   )*PPAD + dq*4];
            float4 p1 = *(const float4*)&pS[(ng+16)*PPAD + dq*4];
            #pragma unroll
            for (int i = 0; i < 2; i++) {
                float4 xv = *(const float4*)&xS[(2*sg+i)*XPAD + dq*4];
                ag[i][0] += xv.x*p0.x + xv.y*p0.y + xv.z*p0.z + xv.w*p0.w;
                ag[i][1] += xv.x*p1.x + xv.y*p1.y + xv.z*p1.z + xv.w*p1.w;
            }
        }
        #pragma unroll
        for (int i = 0; i < 2; i++) {
            cS[(2*sg+i)*CPAD + ng]      = ag[i][0];
            cS[(2*sg+i)*CPAD + ng + 16] = ag[i][1];
        }
    }
    __syncthreads();

    // softmax over n per s-row; 16 warps x 4 rows
    {
        const int wid = t >> 5, lane = t & 31;
        #pragma unroll
        for (int r = 0; r < SCH/16; r++) {
            int s = wid * (SCH/16) + r;
            float lg = cS[s*CPAD + lane];
            size_t li = ((size_t)b * S_ + s0 + s) * N_ + lane;
            if (first) g_logits[li] = lg;
            else       lg += g_logits[li];
            float mx = lg;
            #pragma unroll
            for (int o = 16; o > 0; o >>= 1) mx = fmaxf(mx, __shfl_xor_sync(0xffffffffu, mx, o));
            float e = expf(lg - mx);
            float sum = e;
            #pragma unroll
            for (int o = 16; o > 0; o >>= 1) sum += __shfl_xor_sync(0xffffffffu, sum, o);
            cS[s*CPAD + lane] = e / sum;
        }
    }
    __syncthreads();

    // phase 3: y[n][d] += sum_s c[s][n] * x[s][d]; thread tile 2n x 8d.
    // d = {lane*4 .. +3, lane*4+128 .. +3}: lanes consecutive -> conflict-free;
    // c reads are warp-uniform broadcast.
    {
        const int ng2  = t >> 5;        // 0..15 -> n = 2*ng2, 2*ng2+1
        const int lane = t & 31;
        float acc[2][8];
        #pragma unroll
        for (int i = 0; i < 2; i++)
            #pragma unroll
            for (int j = 0; j < 8; j++) acc[i][j] = 0.f;
        #pragma unroll 2
        for (int s = 0; s < SCH; s++) {
            float4 xa = *(const float4*)&xS[s*XPAD + lane*4];
            float4 xb = *(const float4*)&xS[s*XPAD + lane*4 + 128];
            float2 cv = *(const float2*)&cS[s*CPAD + ng2*2];
            float xr[8] = {xa.x, xa.y, xa.z, xa.w, xb.x, xb.y, xb.z, xb.w};
            #pragma unroll
            for (int j = 0; j < 8; j++) {
                acc[0][j] += cv.x * xr[j];
                acc[1][j] += cv.y * xr[j];
            }
        }
        float* yo = (first ? g_ya : g_yb) + (size_t)b * N_ * D_;
        #pragma unroll
        for (int i = 0; i < 2; i++) {
            #pragma unroll
            for (int j = 0; j < 4; j++) {
                atomicAdd(&yo[(ng2*2 + i)*D_ + lane*4 + j],       acc[i][j]);
                atomicAdd(&yo[(ng2*2 + i)*D_ + lane*4 + 128 + j], acc[i][4+j]);
            }
        }
    }
}

// ---------------- launch ----------------------------------------------------
extern "C" void kernel_launch(void* const* d_in, const int* in_sizes, int n_in,
                              void* d_out, int out_size) {
    (void)in_sizes; (void)n_in; (void)out_size;
    const float* x = (const float*)d_in[0];
    const float* W = (const float*)d_in[1];
    float* out = (float*)d_out;

    cudaFuncSetAttribute(capsule_kernel, cudaFuncAttributeMaxDynamicSharedMemorySize, CAPS_SMEM);
    cudaFuncSetAttribute(pass_kernel,    cudaFuncAttributeMaxDynamicSharedMemorySize, PASS_SMEM);

    zero_kernel<<<(B_*N_*D_ + 255) / 256, 256>>>();
    reduce_x_kernel<<<B_*8, 256>>>(x);                                  // y0

    capsule_kernel<<<dim3(N_, B_/8), 256, CAPS_SMEM>>>(W, 0, nullptr, 1); // v0, p0
    pass_kernel<<<B_*CHUNKS, TPB, PASS_SMEM>>>(x, 1);                     // iter1 -> g_ya, logits
    capsule_kernel<<<dim3(N_, B_/8), 256, CAPS_SMEM>>>(W, 1, nullptr, 1); // v1, p1
    pass_kernel<<<B_*CHUNKS, TPB, PASS_SMEM>>>(x, 0);                     // iter2 -> g_yb
    capsule_kernel<<<dim3(N_, B_/8), 256, CAPS_SMEM>>>(W, 2, out, 0);     // v2 -> d_out
}